// round 2
// baseline (speedup 1.0000x reference)
#include <cuda_runtime.h>
#include <cuda_bf16.h>

// SAR-ADC true-quantization: x[500000,24] f32, W[10] f32 ->
//   q[500000,24] f32  (first 12,000,000 floats of d_out)
//   Q[500000,24,4] f32 (next 48,000,000 floats of d_out)
//
// Pure streaming kernel: 48MB read + 240MB write. One thread handles 4
// consecutive x elements (float4 in, float4 q out, 4x float4 Q out = 64B
// contiguous per thread).

#define LENGTH_ 500000
#define NADC_   24
#define NTOT_   (LENGTH_ * NADC_)   // 12,000,000 (divisible by 4)
#define N4_     (NTOT_ / 4)         // 3,000,000

__device__ __forceinline__ float sar_sign(float v) {
    float t = v + 1e-30f;
    return (t > 0.0f) ? 1.0f : ((t < 0.0f) ? -1.0f : 0.0f);
}

__global__ __launch_bounds__(256)
void sar_quant_kernel(const float4* __restrict__ x4,
                      const float*  __restrict__ W,
                      float4* __restrict__ q4,
                      float4* __restrict__ Qout) {
    int i = blockIdx.x * blockDim.x + threadIdx.x;
    if (i >= N4_) return;

    const float VR = 1.8f / 16.0f;   // LSB voltage; VREF == VR
    // Unrolled weight walk (m = 9 .. 0), all scaled by VR.
    // b_k = (Q_k + 1) * 0.5 carries the 0.5; correction consts are W*VR only.
    const float t3  = W[9] * VR;   // j=3 threshold
    const float t2  = W[8] * VR;   // j=2 base
    const float c23 = W[7] * VR;   //   + b3 term
    const float t1  = W[6] * VR;   // j=1 base
    const float c12 = W[5] * VR;   //   + b2 term
    const float c13 = W[4] * VR;   //   + b3 term
    const float t0  = W[3] * VR;   // j=0 base
    const float c01 = W[2] * VR;   //   + b1 term
    const float c02 = W[1] * VR;   //   + b2 term
    const float c03 = W[0] * VR;   //   + b3 term

    float4 xv = x4[i];
    const float xs[4] = {xv.x, xv.y, xv.z, xv.w};

    float qo[4];
    float4 Qo[4];
    #pragma unroll
    for (int e = 0; e < 4; e++) {
        float xx = xs[e];
        float Q3 = sar_sign(xx - t3);
        float b3 = (Q3 + 1.0f) * 0.5f;
        float Q2 = sar_sign(xx - (t2 + b3 * c23));
        float b2 = (Q2 + 1.0f) * 0.5f;
        float Q1 = sar_sign(xx - (t1 + b2 * c12 + b3 * c13));
        float b1 = (Q1 + 1.0f) * 0.5f;
        float Q0 = sar_sign(xx - (t0 + b1 * c01 + b2 * c02 + b3 * c03));
        float b0 = (Q0 + 1.0f) * 0.5f;
        qo[e] = VR * (b0 + 2.0f * b1 + 4.0f * b2 + 8.0f * b3);
        Qo[e] = make_float4(Q0, Q1, Q2, Q3);
    }

    q4[i] = make_float4(qo[0], qo[1], qo[2], qo[3]);
    // Q layout: [elem][4 bits] contiguous -> thread writes 4 consecutive float4s.
    float4* Qp = Qout + 4 * (size_t)i;
    Qp[0] = Qo[0];
    Qp[1] = Qo[1];
    Qp[2] = Qo[2];
    Qp[3] = Qo[3];
}

extern "C" void kernel_launch(void* const* d_in, const int* in_sizes, int n_in,
                              void* d_out, int out_size) {
    const float4* x4 = (const float4*)d_in[0];
    const float*  W  = (const float*)d_in[1];
    float* out = (float*)d_out;
    float4* q4   = (float4*)out;                 // 12,000,000 floats
    float4* Qout = (float4*)(out + (size_t)NTOT_); // 48,000,000 floats

    const int threads = 256;
    const int blocks  = (N4_ + threads - 1) / threads;
    sar_quant_kernel<<<blocks, threads>>>(x4, W, q4, Qout);
}